// round 3
// baseline (speedup 1.0000x reference)
#include <cuda_runtime.h>
#include <math.h>

#define BB 8
#define CC 3
#define NF 2
#define H0 512
#define W0 1024

#define L0 (512*1024)
#define L1 (256*512)
#define L2 (128*256)
#define L3 (64*128)

// ---- static device scratch (no allocations allowed) ----
// ref_rgb planar pyramid (levels 1..3); level 0 = input directly
__device__ float g_rr1[BB*CC*L1];
__device__ float g_rr2[BB*CC*L2];
__device__ float g_rr3[BB*CC*L3];
// target images interleaved as float4 (r,g,b,0), levels 0..3
__device__ float4 g_t0_0[BB*L0];
__device__ float4 g_t0_1[BB*L1];
__device__ float4 g_t0_2[BB*L2];
__device__ float4 g_t0_3[BB*L3];
__device__ float4 g_t1_0[BB*L0];
__device__ float4 g_t1_1[BB*L1];
__device__ float4 g_t1_2[BB*L2];
__device__ float4 g_t1_3[BB*L3];
// per (b, frame): R (9, row-major) + t (3)
__device__ float g_Rt[BB*NF*12];

// ---------------- pose -> rotation matrices ----------------
__global__ void pose_kernel(const float* __restrict__ pose) {
    int i = threadIdx.x;
    if (i >= BB*NF) return;
    const float* p = pose + i*6;
    float tx = p[0], ty = p[1], tz = p[2];
    float rx = p[3], ry = p[4], rz = p[5];
    float th = sqrtf(rx*rx + ry*ry + rz*rz);
    float inv = 1.0f / fmaxf(th, 1e-8f);
    float kx = rx*inv, ky = ry*inv, kz = rz*inv;
    float s = sinf(th), c = cosf(th), mc = 1.0f - c;
    float* R = g_Rt + i*12;
    R[0] = 1.0f + mc*(-(ky*ky + kz*kz));
    R[1] = -s*kz + mc*(kx*ky);
    R[2] =  s*ky + mc*(kx*kz);
    R[3] =  s*kz + mc*(kx*ky);
    R[4] = 1.0f + mc*(-(kx*kx + kz*kz));
    R[5] = -s*kx + mc*(ky*kz);
    R[6] = -s*ky + mc*(kx*kz);
    R[7] =  s*kx + mc*(ky*kz);
    R[8] = 1.0f + mc*(-(kx*kx + ky*ky));
    R[9] = tx; R[10] = ty; R[11] = tz;
}

// ---------------- planar (B,3,H,W) -> interleaved float4 ----------------
__global__ void interleave_kernel(const float* __restrict__ src, float4* __restrict__ dst) {
    int idx = blockIdx.x * blockDim.x + threadIdx.x;
    if (idx >= BB*L0) return;
    int b = idx / L0, p = idx % L0;
    const float* s = src + (size_t)b*CC*L0 + p;
    dst[idx] = make_float4(s[0], s[L0], s[2*L0], 0.0f);
}

// ---------------- 2x2 area down, float4 ----------------
__global__ void down2_f4(const float4* __restrict__ src, float4* __restrict__ dst, int h2, int w2) {
    int idx = blockIdx.x * blockDim.x + threadIdx.x;
    int n = BB * h2 * w2;
    if (idx >= n) return;
    int b = idx / (h2*w2);
    int p = idx % (h2*w2);
    int y = p / w2, x = p % w2;
    int w = w2 * 2;
    const float4* s = src + ((size_t)b*h2*2 + y*2) * w + x*2;
    float4 a = s[0], bq = s[1], cq = s[w], dq = s[w+1];
    dst[idx] = make_float4(0.25f*(a.x + bq.x + cq.x + dq.x),
                           0.25f*(a.y + bq.y + cq.y + dq.y),
                           0.25f*(a.z + bq.z + cq.z + dq.z),
                           0.0f);
}

// ---------------- 2x2 area down, planar (nimg = 24) ----------------
__global__ void down2_planar(const float* __restrict__ src, float* __restrict__ dst, int h2, int w2) {
    int idx = blockIdx.x * blockDim.x + threadIdx.x;
    int n = BB*CC * h2 * w2;
    if (idx >= n) return;
    int img = idx / (h2*w2);
    int p = idx % (h2*w2);
    int y = p / w2, x = p % w2;
    int w = w2 * 2;
    const float* s = src + ((size_t)img*h2*2 + y*2) * w + x*2;
    dst[idx] = 0.25f*(s[0] + s[1] + s[w] + s[w+1]);
}

__global__ void init_out(float* out) { out[0] = 0.0f; }

__device__ __forceinline__ void tap(const float4* __restrict__ base, int xi, int yi,
                                    int w, int h, float wt,
                                    float& vx, float& vy, float& vz) {
    if (xi >= 0 && xi < w && yi >= 0 && yi < h) {
        float4 t4 = __ldg(base + (size_t)yi*w + xi);
        vx += wt * t4.x; vy += wt * t4.y; vz += wt * t4.z;
    }
}

// ---------------- fused reprojection + bilinear sample + masked L1 + reduce ----------------
__global__ void loss_kernel(const float* __restrict__ depth,
                            const float* __restrict__ mask,
                            const float* __restrict__ rr,
                            const float4* __restrict__ tgA,
                            const float4* __restrict__ tgB,
                            int h, int w, float inv_count,
                            float* __restrict__ out) {
    const float PI = 3.14159265358979323846f;
    int idx = blockIdx.x * blockDim.x + threadIdx.x;
    int hw = h * w;
    float acc = 0.0f;
    if (idx < BB*hw) {
        int b = idx / hw;
        int p = idx % hw;
        int y = p / w, x = p % w;
        float d = depth[idx];
        float lon = ((x + 0.5f) / (float)w * 2.0f - 1.0f) * PI;
        float lat = -(((y + 0.5f) / (float)h) * 2.0f - 1.0f) * (0.5f * PI);
        float slo, clo, sla, cla;
        sincosf(lon, &slo, &clo);
        sincosf(lat, &sla, &cla);
        float px0 = d * (cla * slo);
        float py0 = d * sla;
        float pz0 = d * (cla * clo);
        float r0 = rr[((size_t)b*CC + 0)*hw + p];
        float r1 = rr[((size_t)b*CC + 1)*hw + p];
        float r2 = rr[((size_t)b*CC + 2)*hw + p];
        #pragma unroll
        for (int n = 0; n < NF; n++) {
            const float* Rt = g_Rt + (b*NF + n)*12;
            float px = Rt[0]*px0 + Rt[1]*py0 + Rt[2]*pz0 + Rt[9];
            float py = Rt[3]*px0 + Rt[4]*py0 + Rt[5]*pz0 + Rt[10];
            float pz = Rt[6]*px0 + Rt[7]*py0 + Rt[8]*pz0 + Rt[11];
            float norm = sqrtf(px*px + py*py + pz*pz);
            float lo = atan2f(px, pz);
            float la = asinf(fminf(fmaxf(py / fmaxf(norm, 1e-8f), -1.0f), 1.0f));
            float X = lo * (1.0f / PI);
            float Y = la * (2.0f / PI);
            float gx = (X + 1.0f) * 0.5f * (float)(w - 1);
            float gy = (Y + 1.0f) * 0.5f * (float)(h - 1);
            const float4* tg = (n == 0) ? tgA : tgB;
            const float4* base = tg + (size_t)b*hw;
            float x0f = floorf(gx), y0f = floorf(gy);
            int ix0 = (int)x0f, iy0 = (int)y0f;
            float fx = gx - x0f, fy = gy - y0f;
            float wa = (1.0f - fx) * (1.0f - fy);
            float wb = (1.0f - fx) * fy;
            float wc = fx * (1.0f - fy);
            float wd = fx * fy;
            float vx = 0.0f, vy = 0.0f, vz = 0.0f;
            tap(base, ix0,   iy0,   w, h, wa, vx, vy, vz);
            tap(base, ix0,   iy0+1, w, h, wb, vx, vy, vz);
            tap(base, ix0+1, iy0,   w, h, wc, vx, vy, vz);
            tap(base, ix0+1, iy0+1, w, h, wd, vx, vy, vz);
            float m = mask[((size_t)(b*NF + n))*hw + p];
            acc += m * (fabsf(r0 - vx) + fabsf(r1 - vy) + fabsf(r2 - vz));
        }
    }
    // block reduction
    #pragma unroll
    for (int o = 16; o > 0; o >>= 1) acc += __shfl_down_sync(0xffffffffu, acc, o);
    __shared__ float sh[8];
    int lane = threadIdx.x & 31, wid = threadIdx.x >> 5;
    if (lane == 0) sh[wid] = acc;
    __syncthreads();
    if (wid == 0) {
        acc = (lane < (int)(blockDim.x >> 5)) ? sh[lane] : 0.0f;
        #pragma unroll
        for (int o = 4; o > 0; o >>= 1) acc += __shfl_down_sync(0xffffffffu, acc, o);
        if (lane == 0) atomicAdd(out, acc * inv_count);
    }
}

static inline int cdiv(int a, int b) { return (a + b - 1) / b; }

extern "C" void kernel_launch(void* const* d_in, const int* in_sizes, int n_in,
                              void* d_out, int out_size) {
    // setup_inputs() dict order is INTERLEAVED:
    // [0]=ref_rgb, [1]=ref_depth0, [2]=exp_mask0, [3]=ref_depth1, [4]=exp_mask1,
    // [5]=ref_depth2, [6]=exp_mask2, [7]=ref_depth3, [8]=exp_mask3,
    // [9]=tgt_rgb0, [10]=tgt_rgb1, [11]=pose
    const float* ref   = (const float*)d_in[0];
    const float* dep[4] = {(const float*)d_in[1], (const float*)d_in[3],
                           (const float*)d_in[5], (const float*)d_in[7]};
    const float* msk[4] = {(const float*)d_in[2], (const float*)d_in[4],
                           (const float*)d_in[6], (const float*)d_in[8]};
    const float* tgt0  = (const float*)d_in[9];
    const float* tgt1  = (const float*)d_in[10];
    const float* pose  = (const float*)d_in[11];
    float* out = (float*)d_out;

    float *rr1, *rr2, *rr3;
    float4 *t00, *t01, *t02, *t03, *t10, *t11, *t12, *t13;
    cudaGetSymbolAddress((void**)&rr1, g_rr1);
    cudaGetSymbolAddress((void**)&rr2, g_rr2);
    cudaGetSymbolAddress((void**)&rr3, g_rr3);
    cudaGetSymbolAddress((void**)&t00, g_t0_0);
    cudaGetSymbolAddress((void**)&t01, g_t0_1);
    cudaGetSymbolAddress((void**)&t02, g_t0_2);
    cudaGetSymbolAddress((void**)&t03, g_t0_3);
    cudaGetSymbolAddress((void**)&t10, g_t1_0);
    cudaGetSymbolAddress((void**)&t11, g_t1_1);
    cudaGetSymbolAddress((void**)&t12, g_t1_2);
    cudaGetSymbolAddress((void**)&t13, g_t1_3);

    const int T = 256;

    pose_kernel<<<1, 32>>>(pose);

    interleave_kernel<<<cdiv(BB*L0, T), T>>>(tgt0, t00);
    interleave_kernel<<<cdiv(BB*L0, T), T>>>(tgt1, t10);

    down2_f4<<<cdiv(BB*L1, T), T>>>(t00, t01, 256, 512);
    down2_f4<<<cdiv(BB*L2, T), T>>>(t01, t02, 128, 256);
    down2_f4<<<cdiv(BB*L3, T), T>>>(t02, t03, 64, 128);
    down2_f4<<<cdiv(BB*L1, T), T>>>(t10, t11, 256, 512);
    down2_f4<<<cdiv(BB*L2, T), T>>>(t11, t12, 128, 256);
    down2_f4<<<cdiv(BB*L3, T), T>>>(t12, t13, 64, 128);

    down2_planar<<<cdiv(BB*CC*L1, T), T>>>(ref, rr1, 256, 512);
    down2_planar<<<cdiv(BB*CC*L2, T), T>>>(rr1, rr2, 128, 256);
    down2_planar<<<cdiv(BB*CC*L3, T), T>>>(rr2, rr3, 64, 128);

    init_out<<<1, 1>>>(out);

    loss_kernel<<<cdiv(BB*L0, T), T>>>(dep[0], msk[0], ref, t00, t10, 512, 1024,
                                       1.0f/(float)(BB*CC*L0), out);
    loss_kernel<<<cdiv(BB*L1, T), T>>>(dep[1], msk[1], rr1, t01, t11, 256, 512,
                                       1.0f/(float)(BB*CC*L1), out);
    loss_kernel<<<cdiv(BB*L2, T), T>>>(dep[2], msk[2], rr2, t02, t12, 128, 256,
                                       1.0f/(float)(BB*CC*L2), out);
    loss_kernel<<<cdiv(BB*L3, T), T>>>(dep[3], msk[3], rr3, t03, t13, 64, 128,
                                       1.0f/(float)(BB*CC*L3), out);
}

// round 4
// speedup vs baseline: 1.1077x; 1.1077x over previous
#include <cuda_runtime.h>
#include <math.h>

#define BB 8
#define CC 3
#define NF 2
#define H0 512
#define W0 1024

#define L0 (512*1024)
#define L1 (256*512)
#define L2 (128*256)
#define L3 (64*128)

#define PI_F 3.14159265358979323846f

// ---- static device scratch ----
__device__ float g_rr1[BB*CC*L1];
__device__ float g_rr2[BB*CC*L2];
__device__ float g_rr3[BB*CC*L3];
__device__ float4 g_t0_0[BB*L0];
__device__ float4 g_t0_1[BB*L1];
__device__ float4 g_t0_2[BB*L2];
__device__ float4 g_t0_3[BB*L3];
__device__ float4 g_t1_0[BB*L0];
__device__ float4 g_t1_1[BB*L1];
__device__ float4 g_t1_2[BB*L2];
__device__ float4 g_t1_3[BB*L3];
__device__ float g_Rt[BB*NF*12];
// trig tables: lon (sin,cos) for widths 1024,512,256,128 at offsets 0,1024,1536,1792
//              lat (sin,cos) for heights 512,256,128,64 at offsets 0,512,768,896
__device__ float2 g_lon[1920];
__device__ float2 g_lat[960];

// ---------------- setup: pose matrices + trig tables + out init ----------------
__global__ void setup_kernel(const float* __restrict__ pose, float* __restrict__ out) {
    int idx = blockIdx.x * blockDim.x + threadIdx.x;
    if (idx == 0) out[0] = 0.0f;
    if (idx < BB*NF) {
        const float* p = pose + idx*6;
        float tx = p[0], ty = p[1], tz = p[2];
        float rx = p[3], ry = p[4], rz = p[5];
        float th = sqrtf(rx*rx + ry*ry + rz*rz);
        float inv = 1.0f / fmaxf(th, 1e-8f);
        float kx = rx*inv, ky = ry*inv, kz = rz*inv;
        float s = sinf(th), c = cosf(th), mc = 1.0f - c;
        float* R = g_Rt + idx*12;
        R[0] = 1.0f + mc*(-(ky*ky + kz*kz));
        R[1] = -s*kz + mc*(kx*ky);
        R[2] =  s*ky + mc*(kx*kz);
        R[3] =  s*kz + mc*(kx*ky);
        R[4] = 1.0f + mc*(-(kx*kx + kz*kz));
        R[5] = -s*kx + mc*(ky*kz);
        R[6] = -s*ky + mc*(kx*kz);
        R[7] =  s*kx + mc*(ky*kz);
        R[8] = 1.0f + mc*(-(kx*kx + ky*ky));
        R[9] = tx; R[10] = ty; R[11] = tz;
    }
    if (idx < 1920) {
        int off, w;
        if (idx < 1024)      { off = 0;    w = 1024; }
        else if (idx < 1536) { off = 1024; w = 512;  }
        else if (idx < 1792) { off = 1536; w = 256;  }
        else                 { off = 1792; w = 128;  }
        int x = idx - off;
        float lon = (((float)x + 0.5f) / (float)w * 2.0f - 1.0f) * PI_F;
        g_lon[idx] = make_float2(sinf(lon), cosf(lon));
    } else if (idx < 1920 + 960) {
        int i2 = idx - 1920;
        int off, h;
        if (i2 < 512)      { off = 0;   h = 512; }
        else if (i2 < 768) { off = 512; h = 256; }
        else if (i2 < 896) { off = 768; h = 128; }
        else               { off = 896; h = 64;  }
        int y = i2 - off;
        float lat = -((((float)y + 0.5f) / (float)h) * 2.0f - 1.0f) * (0.5f * PI_F);
        g_lat[i2] = make_float2(sinf(lat), cosf(lat));
    }
}

// ---------------- fused: planar targets -> interleaved f4 level0 + level1 ----------------
// each thread: 4x2 pixel tile of level0. gridDim.z = 16 (b*2+f)
__global__ void tgt_lvl01(const float* __restrict__ t0src, const float* __restrict__ t1src,
                          float4* __restrict__ d00, float4* __restrict__ d10,
                          float4* __restrict__ d01, float4* __restrict__ d11) {
    int z = blockIdx.z;
    int b = z >> 1, f = z & 1;
    const float* src = (f ? t1src : t0src) + (size_t)b*CC*L0;
    float4* dst0 = (f ? d10 : d00) + (size_t)b*L0;
    float4* dst1 = (f ? d11 : d01) + (size_t)b*L1;
    int tid = blockIdx.x * blockDim.x + threadIdx.x;   // < 65536
    int tx = tid & 255;        // W0/4 = 256
    int ty = tid >> 8;         // < H0/2 = 256
    int x0 = tx * 4, y0 = ty * 2;

    float4 a0 = *(const float4*)(src + (size_t)0*L0 + (size_t)y0*W0 + x0);
    float4 b0 = *(const float4*)(src + (size_t)1*L0 + (size_t)y0*W0 + x0);
    float4 c0 = *(const float4*)(src + (size_t)2*L0 + (size_t)y0*W0 + x0);
    float4 a1 = *(const float4*)(src + (size_t)0*L0 + (size_t)(y0+1)*W0 + x0);
    float4 b1 = *(const float4*)(src + (size_t)1*L0 + (size_t)(y0+1)*W0 + x0);
    float4 c1 = *(const float4*)(src + (size_t)2*L0 + (size_t)(y0+1)*W0 + x0);

    float4* o0 = dst0 + (size_t)y0*W0 + x0;
    float4* o1 = dst0 + (size_t)(y0+1)*W0 + x0;
    o0[0] = make_float4(a0.x, b0.x, c0.x, 0.f);
    o0[1] = make_float4(a0.y, b0.y, c0.y, 0.f);
    o0[2] = make_float4(a0.z, b0.z, c0.z, 0.f);
    o0[3] = make_float4(a0.w, b0.w, c0.w, 0.f);
    o1[0] = make_float4(a1.x, b1.x, c1.x, 0.f);
    o1[1] = make_float4(a1.y, b1.y, c1.y, 0.f);
    o1[2] = make_float4(a1.z, b1.z, c1.z, 0.f);
    o1[3] = make_float4(a1.w, b1.w, c1.w, 0.f);

    float4* p1 = dst1 + (size_t)ty*(W0/2) + tx*2;
    p1[0] = make_float4(0.25f*(a0.x + a0.y + a1.x + a1.y),
                        0.25f*(b0.x + b0.y + b1.x + b1.y),
                        0.25f*(c0.x + c0.y + c1.x + c1.y), 0.f);
    p1[1] = make_float4(0.25f*(a0.z + a0.w + a1.z + a1.w),
                        0.25f*(b0.z + b0.w + b1.z + b1.w),
                        0.25f*(c0.z + c0.w + c1.z + c1.w), 0.f);
}

// ---------------- 2x2 area down, float4, both frames via z ----------------
__global__ void down2_f4_2(const float4* __restrict__ s0, const float4* __restrict__ s1,
                           float4* __restrict__ d0, float4* __restrict__ d1,
                           int h2, int w2) {
    int idx = blockIdx.x * blockDim.x + threadIdx.x;
    int n = BB * h2 * w2;
    if (idx >= n) return;
    const float4* src = blockIdx.z ? s1 : s0;
    float4* dst = blockIdx.z ? d1 : d0;
    int b = idx / (h2*w2);
    int p = idx % (h2*w2);
    int y = p / w2, x = p % w2;
    int w = w2 * 2;
    const float4* s = src + ((size_t)b*h2*2 + y*2) * w + x*2;
    float4 a = s[0], bq = s[1], cq = s[w], dq = s[w+1];
    dst[idx] = make_float4(0.25f*(a.x + bq.x + cq.x + dq.x),
                           0.25f*(a.y + bq.y + cq.y + dq.y),
                           0.25f*(a.z + bq.z + cq.z + dq.z),
                           0.0f);
}

// ---------------- 2x2 area down, planar ----------------
__global__ void down2_planar(const float* __restrict__ src, float* __restrict__ dst, int h2, int w2) {
    int idx = blockIdx.x * blockDim.x + threadIdx.x;
    int n = BB*CC * h2 * w2;
    if (idx >= n) return;
    int img = idx / (h2*w2);
    int p = idx % (h2*w2);
    int y = p / w2, x = p % w2;
    int w = w2 * 2;
    const float* s = src + ((size_t)img*h2*2 + y*2) * w + x*2;
    dst[idx] = 0.25f*(s[0] + s[1] + s[w] + s[w+1]);
}

// ---------------- fast atan2 (Cephes-style, ~1e-7 rad) ----------------
__device__ __forceinline__ float atan_poly(float x) {
    // |x| <= 0.4142135: cephes atanf core polynomial
    float z = x * x;
    float r = fmaf(8.05374449538e-2f, z, -1.38776856032e-1f);
    r = fmaf(r, z, 1.99777106478e-1f);
    r = fmaf(r, z, -3.33329491539e-1f);
    return fmaf(r * z, x, x);
}
__device__ __forceinline__ float fast_atan2f(float y, float x) {
    float ay = fabsf(y), ax = fabsf(x);
    float mx = fmaxf(ax, ay), mn = fminf(ax, ay);
    float t = __fdividef(mn, mx);                 // [0,1]
    float u = __fdividef(t - 1.0f, t + 1.0f);     // [-1,0]
    bool big = t > 0.41421356f;
    float arg = big ? u : t;
    float r = atan_poly(arg) + (big ? 0.78539816339744831f : 0.0f);
    if (ay > ax) r = 1.57079632679489662f - r;
    if (x < 0.0f) r = PI_F - r;
    return copysignf(r, y);
}

__device__ __forceinline__ void tap(const float4* __restrict__ base, int xi, int yi,
                                    int w, int h, float wt,
                                    float& vx, float& vy, float& vz) {
    if (xi >= 0 && xi < w && yi >= 0 && yi < h) {
        float4 t4 = __ldg(base + (size_t)yi*w + xi);
        vx += wt * t4.x; vy += wt * t4.y; vz += wt * t4.z;
    }
}

// ---------------- fused reprojection + bilinear + masked L1 + reduce ----------------
__global__ void loss_kernel(const float* __restrict__ depth,
                            const float* __restrict__ mask,
                            const float* __restrict__ rr,
                            const float4* __restrict__ tgA,
                            const float4* __restrict__ tgB,
                            const float2* __restrict__ lonT,
                            const float2* __restrict__ latT,
                            int h, int w, float inv_count,
                            float* __restrict__ out) {
    int idx = blockIdx.x * blockDim.x + threadIdx.x;
    int hw = h * w;
    float acc = 0.0f;
    if (idx < BB*hw) {
        int b = idx / hw;
        int p = idx % hw;
        int y = p / w, x = p % w;
        float d = depth[idx];
        float2 lo2 = __ldg(lonT + x);   // (sin, cos) of lon
        float2 la2 = __ldg(latT + y);   // (sin, cos) of lat
        float px0 = d * (la2.y * lo2.x);
        float py0 = d * la2.x;
        float pz0 = d * (la2.y * lo2.y);
        float r0 = rr[((size_t)b*CC + 0)*hw + p];
        float r1 = rr[((size_t)b*CC + 1)*hw + p];
        float r2 = rr[((size_t)b*CC + 2)*hw + p];
        #pragma unroll
        for (int n = 0; n < NF; n++) {
            const float* Rt = g_Rt + (b*NF + n)*12;
            float px = Rt[0]*px0 + Rt[1]*py0 + Rt[2]*pz0 + Rt[9];
            float py = Rt[3]*px0 + Rt[4]*py0 + Rt[5]*pz0 + Rt[10];
            float pz = Rt[6]*px0 + Rt[7]*py0 + Rt[8]*pz0 + Rt[11];
            float lo = fast_atan2f(px, pz);
            float sxz = sqrtf(px*px + pz*pz);
            float la = fast_atan2f(py, sxz);   // == asin(py/norm)
            float gx = fmaf(lo, (1.0f/PI_F), 1.0f) * (0.5f * (float)(w - 1));
            float gy = fmaf(la, (2.0f/PI_F), 1.0f) * (0.5f * (float)(h - 1));
            const float4* base = ((n == 0) ? tgA : tgB) + (size_t)b*hw;
            float x0f = floorf(gx), y0f = floorf(gy);
            int ix0 = (int)x0f, iy0 = (int)y0f;
            float fx = gx - x0f, fy = gy - y0f;
            float wa = (1.0f - fx) * (1.0f - fy);
            float wb = (1.0f - fx) * fy;
            float wc = fx * (1.0f - fy);
            float wd = fx * fy;
            float vx = 0.0f, vy = 0.0f, vz = 0.0f;
            tap(base, ix0,   iy0,   w, h, wa, vx, vy, vz);
            tap(base, ix0,   iy0+1, w, h, wb, vx, vy, vz);
            tap(base, ix0+1, iy0,   w, h, wc, vx, vy, vz);
            tap(base, ix0+1, iy0+1, w, h, wd, vx, vy, vz);
            float m = mask[((size_t)(b*NF + n))*hw + p];
            acc += m * (fabsf(r0 - vx) + fabsf(r1 - vy) + fabsf(r2 - vz));
        }
    }
    #pragma unroll
    for (int o = 16; o > 0; o >>= 1) acc += __shfl_down_sync(0xffffffffu, acc, o);
    __shared__ float sh[8];
    int lane = threadIdx.x & 31, wid = threadIdx.x >> 5;
    if (lane == 0) sh[wid] = acc;
    __syncthreads();
    if (wid == 0) {
        acc = (lane < (int)(blockDim.x >> 5)) ? sh[lane] : 0.0f;
        #pragma unroll
        for (int o = 4; o > 0; o >>= 1) acc += __shfl_down_sync(0xffffffffu, acc, o);
        if (lane == 0) atomicAdd(out, acc * inv_count);
    }
}

static inline int cdiv(int a, int b) { return (a + b - 1) / b; }

extern "C" void kernel_launch(void* const* d_in, const int* in_sizes, int n_in,
                              void* d_out, int out_size) {
    // interleaved input order:
    // [0]=ref_rgb, [1]=depth0, [2]=mask0, [3]=depth1, [4]=mask1,
    // [5]=depth2, [6]=mask2, [7]=depth3, [8]=mask3, [9]=tgt0, [10]=tgt1, [11]=pose
    const float* ref   = (const float*)d_in[0];
    const float* dep[4] = {(const float*)d_in[1], (const float*)d_in[3],
                           (const float*)d_in[5], (const float*)d_in[7]};
    const float* msk[4] = {(const float*)d_in[2], (const float*)d_in[4],
                           (const float*)d_in[6], (const float*)d_in[8]};
    const float* tgt0  = (const float*)d_in[9];
    const float* tgt1  = (const float*)d_in[10];
    const float* pose  = (const float*)d_in[11];
    float* out = (float*)d_out;

    float *rr1, *rr2, *rr3;
    float4 *t00, *t01, *t02, *t03, *t10, *t11, *t12, *t13;
    float2 *lonT, *latT;
    cudaGetSymbolAddress((void**)&rr1, g_rr1);
    cudaGetSymbolAddress((void**)&rr2, g_rr2);
    cudaGetSymbolAddress((void**)&rr3, g_rr3);
    cudaGetSymbolAddress((void**)&t00, g_t0_0);
    cudaGetSymbolAddress((void**)&t01, g_t0_1);
    cudaGetSymbolAddress((void**)&t02, g_t0_2);
    cudaGetSymbolAddress((void**)&t03, g_t0_3);
    cudaGetSymbolAddress((void**)&t10, g_t1_0);
    cudaGetSymbolAddress((void**)&t11, g_t1_1);
    cudaGetSymbolAddress((void**)&t12, g_t1_2);
    cudaGetSymbolAddress((void**)&t13, g_t1_3);
    cudaGetSymbolAddress((void**)&lonT, g_lon);
    cudaGetSymbolAddress((void**)&latT, g_lat);

    const int T = 256;
    const int lonOff[4] = {0, 1024, 1536, 1792};
    const int latOff[4] = {0, 512, 768, 896};

    setup_kernel<<<12, T>>>(pose, out);

    tgt_lvl01<<<dim3(256, 1, 16), T>>>(tgt0, tgt1, t00, t10, t01, t11);

    down2_f4_2<<<dim3(cdiv(BB*L2, T), 1, 2), T>>>(t01, t11, t02, t12, 128, 256);
    down2_f4_2<<<dim3(cdiv(BB*L3, T), 1, 2), T>>>(t02, t12, t03, t13, 64, 128);

    down2_planar<<<cdiv(BB*CC*L1, T), T>>>(ref, rr1, 256, 512);
    down2_planar<<<cdiv(BB*CC*L2, T), T>>>(rr1, rr2, 128, 256);
    down2_planar<<<cdiv(BB*CC*L3, T), T>>>(rr2, rr3, 64, 128);

    loss_kernel<<<cdiv(BB*L0, T), T>>>(dep[0], msk[0], ref, t00, t10,
                                       lonT + lonOff[0], latT + latOff[0],
                                       512, 1024, 1.0f/(float)(BB*CC*L0), out);
    loss_kernel<<<cdiv(BB*L1, T), T>>>(dep[1], msk[1], rr1, t01, t11,
                                       lonT + lonOff[1], latT + latOff[1],
                                       256, 512, 1.0f/(float)(BB*CC*L1), out);
    loss_kernel<<<cdiv(BB*L2, T), T>>>(dep[2], msk[2], rr2, t02, t12,
                                       lonT + lonOff[2], latT + latOff[2],
                                       128, 256, 1.0f/(float)(BB*CC*L2), out);
    loss_kernel<<<cdiv(BB*L3, T), T>>>(dep[3], msk[3], rr3, t03, t13,
                                       lonT + lonOff[3], latT + latOff[3],
                                       64, 128, 1.0f/(float)(BB*CC*L3), out);
}